// round 11
// baseline (speedup 1.0000x reference)
#include <cuda_runtime.h>
#include <cuda_bf16.h>
#include <cstdint>

// LBP layer, fully fused, warp-strip, two s-columns per lane, edge-specialized,
// integer-mask compare counting (set.ge.s32.f32 + IADD3 tree), packed f32x2 LBP.
//   gray = dot(rgb, [0.2989, 0.587, 0.114])                (zero-padded outside)
//   s(y,x) = #{3x3 nbrs (incl. center): gray >= gray(y,x)} (s = 0 outside image)
//   lbp(y,x) = 1*s(y-1,x-1)+2*s(y-1,x)+4*s(y-1,x+1)
//            +128*s(y,x-1)           +8*s(y,x+1)
//            +64*s(y+1,x-1)+32*s(y+1,x)+16*s(y+1,x+1)
// Fixed shapes: N=32, H=W=512, C=3. Output [N,H,W,1] fp32.

#define OUT_PW   60
#define RPW      8
#define NWARPS   4
#define TILE_H   (RPW * NWARPS)        // 32
#define G_COLS   68
#define G_STRIDE 68
#define G_ROWS   (TILE_H + 4)          // 36
#define NTHREADS 128
#define GX 9
#define GY 16

typedef unsigned long long ull;

// ordered >= compare, integer mask result (-1 true / 0 false), single FSET op
__device__ __forceinline__ int fge(float a, float b) {
    int m;
    asm("set.ge.s32.f32 %0, %1, %2;" : "=r"(m) : "f"(a), "f"(b));
    return m;
}

// packed-f32x2 helpers
__device__ __forceinline__ ull pk2(float lo, float hi) {
    ull r;
    asm("mov.b64 %0, {%1, %2};" : "=l"(r) : "f"(lo), "f"(hi));
    return r;
}
__device__ __forceinline__ ull ffma2(ull a, ull b, ull c) {
    ull d;
    asm("fma.rn.f32x2 %0, %1, %2, %3;" : "=l"(d) : "l"(a), "l"(b), "l"(c));
    return d;
}
__device__ __forceinline__ ull fmul2(ull a, ull b) {
    ull d;
    asm("mul.rn.f32x2 %0, %1, %2;" : "=l"(d) : "l"(a), "l"(b));
    return d;
}

// weight constants, same fp32 value in both halves
#define WPK(bits) ((((ull)(bits)) << 32) | (ull)(bits))
__device__ const ull W2q   = WPK(0x40000000u);   // (2,2)
__device__ const ull W4q   = WPK(0x40800000u);   // (4,4)
__device__ const ull W8q   = WPK(0x41000000u);   // (8,8)
__device__ const ull W16q  = WPK(0x41800000u);   // (16,16)
__device__ const ull W32q  = WPK(0x42000000u);   // (32,32)
__device__ const ull W64q  = WPK(0x42800000u);   // (64,64)
__device__ const ull W128q = WPK(0x43000000u);   // (128,128)

// Fused neighbor-count + LBP stencil, rolling packed registers, shuffle exchange.
template<bool XE, bool YE>
__device__ __forceinline__ void lbp_phase23(
    const float* __restrict__ g, float* __restrict__ outn,
    int x0, int by, int wrp, int lane, int H, int W)
{
    const int csA = x0 - 1 + 2 * lane;
    const bool colA = XE ? ((unsigned)csA < (unsigned)W) : true;
    const bool colB = XE ? ((unsigned)(csA + 1) < (unsigned)W) : true;
    const int r0 = by * TILE_H + wrp * RPW;

    const float* gp = &g[(wrp * RPW) * G_STRIDE + 2 + 2 * lane];

    float2 va = *(const float2*)(gp);     float2 va2 = *(const float2*)(gp + 2);
    float a0 = va.x, a1 = va.y, a2 = va2.x, a3 = va2.y;   gp += G_STRIDE;
    float2 vb = *(const float2*)(gp);     float2 vb2 = *(const float2*)(gp + 2);
    float b0 = vb.x, b1 = vb.y, b2 = vb2.x, b3 = vb2.y;   gp += G_STRIDE;

    // packed s-pair rolling state: P1=(sa,sb) P2=(sb,na) P3=(na,nb)
    ull Q1 = 0, Q2 = 0, Q3 = 0;
    ull R1 = 0, R2 = 0, R3 = 0;

    const bool doStore = (lane <= 29);   // lanes 0..29 -> cols x0 .. x0+59
    float* op = outn + (size_t)r0 * W + (x0 + 2 * lane);

    #pragma unroll
    for (int i = 0; i < RPW + 2; i++) {
        const float2 vt  = *(const float2*)(gp);
        const float2 vt2 = *(const float2*)(gp + 2);
        const float t0 = vt.x, t1 = vt.y, t2 = vt2.x, t3 = vt2.y;
        gp += G_STRIDE;

        // integer mask counting: 8 independent FSETs + add tree per chain
        const int mA = fge(a0, b1) + fge(a1, b1) + fge(a2, b1)
                     + fge(b0, b1) + fge(b2, b1)
                     + fge(t0, b1) + fge(t1, b1) + fge(t2, b1);
        const int mB = fge(a1, b2) + fge(a2, b2) + fge(a3, b2)
                     + fge(b1, b2) + fge(b3, b2)
                     + fge(t1, b2) + fge(t2, b2) + fge(t3, b2);
        const float cA = (float)(1 - mA);    // 1 + #true (center always true)
        const float cB = (float)(1 - mB);

        float sa, sb;
        if (YE) {
            const int ys = r0 - 1 + i;
            const bool rowOk = (unsigned)ys < (unsigned)H;
            sa = (rowOk && colA) ? cA : 0.0f;     // zero-pad s
            sb = (rowOk && colB) ? cB : 0.0f;
        } else if (XE) {
            sa = colA ? cA : 0.0f;
            sb = colB ? cB : 0.0f;
        } else {
            sa = cA;
            sb = cB;
        }

        const float na = __shfl_down_sync(0xffffffffu, sa, 1);  // s col csA+2
        const float nb = __shfl_down_sync(0xffffffffu, sb, 1);  // s col csA+3

        const ull P1 = pk2(sa, sb);
        const ull P2 = pk2(sb, na);
        const ull P3 = pk2(na, nb);

        if (i >= 2) {
            // (v0,v1) = 1*Q1 + 2*Q2 + 4*Q3 + 128*R1 + 8*R3 + 64*P1 + 32*P2 + 16*P3
            ull vA = Q1;
            vA = ffma2(Q2, W2q,   vA);
            vA = ffma2(Q3, W4q,   vA);
            vA = ffma2(R1, W128q, vA);
            ull vB = fmul2(R3, W8q);
            vB = ffma2(P1, W64q, vB);
            vB = ffma2(P2, W32q, vB);
            vB = ffma2(P3, W16q, vB);
            ull v;
            asm("add.rn.f32x2 %0, %1, %2;" : "=l"(v) : "l"(vA), "l"(vB));
            if (doStore) *(ull*)op = v;            // two fp32 outputs, 8B aligned
            op += W;
        }

        Q1 = R1; Q2 = R2; Q3 = R3;
        R1 = P1; R2 = P2; R3 = P3;
        a0 = b0; a1 = b1; a2 = b2; a3 = b3;
        b0 = t0; b1 = t1; b2 = t2; b3 = t3;
    }
}

__global__ __launch_bounds__(NTHREADS, 10) void lbp_warp2_kernel(
    const float* __restrict__ in,   // [N, H, W, 3]
    float* __restrict__ out,        // [N, H, W, 1]
    int H, int W)
{
    __shared__ __align__(16) float g[G_ROWS * G_STRIDE];   // 9.56 KB

    const int tid  = threadIdx.x;
    const int lane = tid & 31;
    const int wrp  = tid >> 5;
    const int bx = blockIdx.x, by = blockIdx.y, n = blockIdx.z;

    const bool xe = (bx == 0) || (bx == GX - 1);
    const bool ye = (by == 0) || (by == GY - 1);

    int x0 = bx * OUT_PW;
    if (x0 + OUT_PW > W) x0 = W - OUT_PW;     // 452 for last block (%4==0)
    const int gx0a = x0 - 4;
    const int gy0 = by * TILE_H - 2;

    const float* __restrict__ base = in + (size_t)n * H * W * 3;

    // ---------------- Phase 1: RGB -> gray into smem ----------------
    if (!xe) {
        if (!ye) {
            #pragma unroll 4
            for (int idx = tid; idx < G_ROWS * (G_COLS / 4); idx += NTHREADS) {
                const int r  = idx / (G_COLS / 4);
                const int pc = idx - r * (G_COLS / 4);
                const int gy = gy0 + r;
                const int gx = gx0a + 4 * pc;
                const float4* p = (const float4*)(base + ((size_t)gy * W + gx) * 3);
                const float4 q0 = __ldg(p + 0);
                const float4 q1 = __ldg(p + 1);
                const float4 q2 = __ldg(p + 2);
                float4 go;
                go.x = fmaf(0.2989f, q0.x, fmaf(0.587f, q0.y, 0.114f * q0.z));
                go.y = fmaf(0.2989f, q0.w, fmaf(0.587f, q1.x, 0.114f * q1.y));
                go.z = fmaf(0.2989f, q1.z, fmaf(0.587f, q1.w, 0.114f * q2.x));
                go.w = fmaf(0.2989f, q2.y, fmaf(0.587f, q2.z, 0.114f * q2.w));
                *(float4*)&g[r * G_STRIDE + 4 * pc] = go;
            }
        } else {
            #pragma unroll 4
            for (int idx = tid; idx < G_ROWS * (G_COLS / 4); idx += NTHREADS) {
                const int r  = idx / (G_COLS / 4);
                const int pc = idx - r * (G_COLS / 4);
                const int gy = gy0 + r;
                float4 go = make_float4(0.f, 0.f, 0.f, 0.f);
                if ((unsigned)gy < (unsigned)H) {
                    const int gx = gx0a + 4 * pc;
                    const float4* p = (const float4*)(base + ((size_t)gy * W + gx) * 3);
                    const float4 q0 = __ldg(p + 0);
                    const float4 q1 = __ldg(p + 1);
                    const float4 q2 = __ldg(p + 2);
                    go.x = fmaf(0.2989f, q0.x, fmaf(0.587f, q0.y, 0.114f * q0.z));
                    go.y = fmaf(0.2989f, q0.w, fmaf(0.587f, q1.x, 0.114f * q1.y));
                    go.z = fmaf(0.2989f, q1.z, fmaf(0.587f, q1.w, 0.114f * q2.x));
                    go.w = fmaf(0.2989f, q2.y, fmaf(0.587f, q2.z, 0.114f * q2.w));
                }
                *(float4*)&g[r * G_STRIDE + 4 * pc] = go;
            }
        }
    } else {
        #pragma unroll 4
        for (int idx = tid; idx < G_ROWS * G_COLS; idx += NTHREADS) {
            const int r = idx / G_COLS;
            const int c = idx - r * G_COLS;
            const int gy = gy0 + r;
            const int gx = gx0a + c;
            float v = 0.0f;
            if ((unsigned)gy < (unsigned)H && (unsigned)gx < (unsigned)W) {
                const float* p = base + ((size_t)gy * W + gx) * 3;
                v = fmaf(0.2989f, __ldg(p), fmaf(0.587f, __ldg(p + 1), 0.114f * __ldg(p + 2)));
            }
            g[r * G_STRIDE + c] = v;
        }
    }
    __syncthreads();

    // ------------- Phase 2+3 fused: specialized per block class -------------
    float* outn = out + (size_t)n * H * W;
    if (!xe && !ye)      lbp_phase23<false, false>(g, outn, x0, by, wrp, lane, H, W);
    else if (!xe)        lbp_phase23<false, true >(g, outn, x0, by, wrp, lane, H, W);
    else if (!ye)        lbp_phase23<true,  false>(g, outn, x0, by, wrp, lane, H, W);
    else                 lbp_phase23<true,  true >(g, outn, x0, by, wrp, lane, H, W);
}

extern "C" void kernel_launch(void* const* d_in, const int* in_sizes, int n_in,
                              void* d_out, int out_size)
{
    const float* in = (const float*)d_in[0];
    float* out = (float*)d_out;

    const int H = 512, W = 512;
    const int N = in_sizes[0] / (H * W * 3);

    dim3 grid(GX, GY, N);   // 9 x 16 x 32 = 4608
    lbp_warp2_kernel<<<grid, NTHREADS>>>(in, out, H, W);
}

// round 12
// speedup vs baseline: 1.0828x; 1.0828x over previous
#include <cuda_runtime.h>
#include <cuda_bf16.h>
#include <cstdint>

// LBP layer, fully fused, warp-strip, two s-columns per lane, edge-specialized,
// packed f32x2 LBP accumulation, RPW=16 (deep rolling strips).
//   gray = dot(rgb, [0.2989, 0.587, 0.114])                (zero-padded outside)
//   s(y,x) = #{3x3 nbrs (incl. center): gray >= gray(y,x)} (s = 0 outside image)
//   lbp(y,x) = 1*s(y-1,x-1)+2*s(y-1,x)+4*s(y-1,x+1)
//            +128*s(y,x-1)           +8*s(y,x+1)
//            +64*s(y+1,x-1)+32*s(y+1,x)+16*s(y+1,x+1)
// Fixed shapes: N=32, H=W=512, C=3. Output [N,H,W,1] fp32.

#define OUT_PW   60
#define RPW      16
#define NWARPS   4
#define TILE_H   (RPW * NWARPS)        // 64
#define G_COLS   68
#define G_STRIDE 68
#define G_ROWS   (TILE_H + 4)          // 68
#define NTHREADS 128
#define GX 9
#define GY 8

typedef unsigned long long ull;

// packed-f32x2 helpers
__device__ __forceinline__ ull pk2(float lo, float hi) {
    ull r;
    asm("mov.b64 %0, {%1, %2};" : "=l"(r) : "f"(lo), "f"(hi));
    return r;
}
__device__ __forceinline__ ull ffma2(ull a, ull b, ull c) {
    ull d;
    asm("fma.rn.f32x2 %0, %1, %2, %3;" : "=l"(d) : "l"(a), "l"(b), "l"(c));
    return d;
}
__device__ __forceinline__ ull fmul2(ull a, ull b) {
    ull d;
    asm("mul.rn.f32x2 %0, %1, %2;" : "=l"(d) : "l"(a), "l"(b));
    return d;
}

// weight constants, same fp32 value in both halves
#define WPK(bits) ((((ull)(bits)) << 32) | (ull)(bits))
__device__ const ull W2q   = WPK(0x40000000u);   // (2,2)
__device__ const ull W4q   = WPK(0x40800000u);   // (4,4)
__device__ const ull W8q   = WPK(0x41000000u);   // (8,8)
__device__ const ull W16q  = WPK(0x41800000u);   // (16,16)
__device__ const ull W32q  = WPK(0x42000000u);   // (32,32)
__device__ const ull W64q  = WPK(0x42800000u);   // (64,64)
__device__ const ull W128q = WPK(0x43000000u);   // (128,128)

// Fused neighbor-count + LBP stencil, rolling packed registers, shuffle exchange.
template<bool XE, bool YE>
__device__ __forceinline__ void lbp_phase23(
    const float* __restrict__ g, float* __restrict__ outn,
    int x0, int by, int wrp, int lane, int H, int W)
{
    const int csA = x0 - 1 + 2 * lane;
    const bool colA = XE ? ((unsigned)csA < (unsigned)W) : true;
    const bool colB = XE ? ((unsigned)(csA + 1) < (unsigned)W) : true;
    const int r0 = by * TILE_H + wrp * RPW;

    const float* gp = &g[(wrp * RPW) * G_STRIDE + 2 + 2 * lane];

    float2 va = *(const float2*)(gp);     float2 va2 = *(const float2*)(gp + 2);
    float a0 = va.x, a1 = va.y, a2 = va2.x, a3 = va2.y;   gp += G_STRIDE;
    float2 vb = *(const float2*)(gp);     float2 vb2 = *(const float2*)(gp + 2);
    float b0 = vb.x, b1 = vb.y, b2 = vb2.x, b3 = vb2.y;   gp += G_STRIDE;

    // packed s-pair rolling state: P1=(sa,sb) P2=(sb,na) P3=(na,nb)
    // Q* = two iters ago (weights 1/2/4), R* = one iter ago (128/-/8)
    ull Q1 = 0, Q2 = 0, Q3 = 0;
    ull R1 = 0, R2 = 0, R3 = 0;

    const bool doStore = (lane <= 29);   // lanes 0..29 -> cols x0 .. x0+59
    float* op = outn + (size_t)r0 * W + (x0 + 2 * lane);

    #pragma unroll
    for (int i = 0; i < RPW + 2; i++) {
        const float2 vt  = *(const float2*)(gp);
        const float2 vt2 = *(const float2*)(gp + 2);
        const float t0 = vt.x, t1 = vt.y, t2 = vt2.x, t3 = vt2.y;
        gp += G_STRIDE;

        // two independent compare-accumulate chains (centers b1, b2)
        float cA = 1.0f, cB = 1.0f;
        cA += (a0 >= b1) ? 1.0f : 0.0f;
        cB += (a1 >= b2) ? 1.0f : 0.0f;
        cA += (a1 >= b1) ? 1.0f : 0.0f;
        cB += (a2 >= b2) ? 1.0f : 0.0f;
        cA += (a2 >= b1) ? 1.0f : 0.0f;
        cB += (a3 >= b2) ? 1.0f : 0.0f;
        cA += (b0 >= b1) ? 1.0f : 0.0f;
        cB += (b1 >= b2) ? 1.0f : 0.0f;
        cA += (b2 >= b1) ? 1.0f : 0.0f;
        cB += (b3 >= b2) ? 1.0f : 0.0f;
        cA += (t0 >= b1) ? 1.0f : 0.0f;
        cB += (t1 >= b2) ? 1.0f : 0.0f;
        cA += (t1 >= b1) ? 1.0f : 0.0f;
        cB += (t2 >= b2) ? 1.0f : 0.0f;
        cA += (t2 >= b1) ? 1.0f : 0.0f;
        cB += (t3 >= b2) ? 1.0f : 0.0f;

        float sa, sb;
        if (YE) {
            const int ys = r0 - 1 + i;
            const bool rowOk = (unsigned)ys < (unsigned)H;
            sa = (rowOk && colA) ? cA : 0.0f;     // zero-pad s
            sb = (rowOk && colB) ? cB : 0.0f;
        } else if (XE) {
            sa = colA ? cA : 0.0f;
            sb = colB ? cB : 0.0f;
        } else {
            sa = cA;
            sb = cB;
        }

        const float na = __shfl_down_sync(0xffffffffu, sa, 1);  // s col csA+2
        const float nb = __shfl_down_sync(0xffffffffu, sb, 1);  // s col csA+3

        const ull P1 = pk2(sa, sb);
        const ull P2 = pk2(sb, na);
        const ull P3 = pk2(na, nb);

        if (i >= 2) {
            // (v0,v1) = 1*Q1 + 2*Q2 + 4*Q3 + 128*R1 + 8*R3 + 64*P1 + 32*P2 + 16*P3
            ull vA = Q1;
            vA = ffma2(Q2, W2q,   vA);
            vA = ffma2(Q3, W4q,   vA);
            vA = ffma2(R1, W128q, vA);
            ull vB = fmul2(R3, W8q);
            vB = ffma2(P1, W64q, vB);
            vB = ffma2(P2, W32q, vB);
            vB = ffma2(P3, W16q, vB);
            ull v;
            asm("add.rn.f32x2 %0, %1, %2;" : "=l"(v) : "l"(vA), "l"(vB));
            if (doStore) *(ull*)op = v;            // two fp32 outputs, 8B aligned
            op += W;
        }

        Q1 = R1; Q2 = R2; Q3 = R3;
        R1 = P1; R2 = P2; R3 = P3;
        a0 = b0; a1 = b1; a2 = b2; a3 = b3;
        b0 = t0; b1 = t1; b2 = t2; b3 = t3;
    }
}

__global__ __launch_bounds__(NTHREADS, 10) void lbp_warp2_kernel(
    const float* __restrict__ in,   // [N, H, W, 3]
    float* __restrict__ out,        // [N, H, W, 1]
    int H, int W)
{
    __shared__ __align__(16) float g[G_ROWS * G_STRIDE];   // 18.5 KB

    const int tid  = threadIdx.x;
    const int lane = tid & 31;
    const int wrp  = tid >> 5;
    const int bx = blockIdx.x, by = blockIdx.y, n = blockIdx.z;

    const bool xe = (bx == 0) || (bx == GX - 1);
    const bool ye = (by == 0) || (by == GY - 1);

    int x0 = bx * OUT_PW;
    if (x0 + OUT_PW > W) x0 = W - OUT_PW;     // 452 for last block (%4==0)
    const int gx0a = x0 - 4;
    const int gy0 = by * TILE_H - 2;

    const float* __restrict__ base = in + (size_t)n * H * W * 3;

    // ---------------- Phase 1: RGB -> gray into smem ----------------
    if (!xe) {
        if (!ye) {
            #pragma unroll 4
            for (int idx = tid; idx < G_ROWS * (G_COLS / 4); idx += NTHREADS) {
                const int r  = idx / (G_COLS / 4);
                const int pc = idx - r * (G_COLS / 4);
                const int gy = gy0 + r;
                const int gx = gx0a + 4 * pc;
                const float4* p = (const float4*)(base + ((size_t)gy * W + gx) * 3);
                const float4 q0 = __ldg(p + 0);
                const float4 q1 = __ldg(p + 1);
                const float4 q2 = __ldg(p + 2);
                float4 go;
                go.x = fmaf(0.2989f, q0.x, fmaf(0.587f, q0.y, 0.114f * q0.z));
                go.y = fmaf(0.2989f, q0.w, fmaf(0.587f, q1.x, 0.114f * q1.y));
                go.z = fmaf(0.2989f, q1.z, fmaf(0.587f, q1.w, 0.114f * q2.x));
                go.w = fmaf(0.2989f, q2.y, fmaf(0.587f, q2.z, 0.114f * q2.w));
                *(float4*)&g[r * G_STRIDE + 4 * pc] = go;
            }
        } else {
            #pragma unroll 4
            for (int idx = tid; idx < G_ROWS * (G_COLS / 4); idx += NTHREADS) {
                const int r  = idx / (G_COLS / 4);
                const int pc = idx - r * (G_COLS / 4);
                const int gy = gy0 + r;
                float4 go = make_float4(0.f, 0.f, 0.f, 0.f);
                if ((unsigned)gy < (unsigned)H) {
                    const int gx = gx0a + 4 * pc;
                    const float4* p = (const float4*)(base + ((size_t)gy * W + gx) * 3);
                    const float4 q0 = __ldg(p + 0);
                    const float4 q1 = __ldg(p + 1);
                    const float4 q2 = __ldg(p + 2);
                    go.x = fmaf(0.2989f, q0.x, fmaf(0.587f, q0.y, 0.114f * q0.z));
                    go.y = fmaf(0.2989f, q0.w, fmaf(0.587f, q1.x, 0.114f * q1.y));
                    go.z = fmaf(0.2989f, q1.z, fmaf(0.587f, q1.w, 0.114f * q2.x));
                    go.w = fmaf(0.2989f, q2.y, fmaf(0.587f, q2.z, 0.114f * q2.w));
                }
                *(float4*)&g[r * G_STRIDE + 4 * pc] = go;
            }
        }
    } else {
        #pragma unroll 4
        for (int idx = tid; idx < G_ROWS * G_COLS; idx += NTHREADS) {
            const int r = idx / G_COLS;
            const int c = idx - r * G_COLS;
            const int gy = gy0 + r;
            const int gx = gx0a + c;
            float v = 0.0f;
            if ((unsigned)gy < (unsigned)H && (unsigned)gx < (unsigned)W) {
                const float* p = base + ((size_t)gy * W + gx) * 3;
                v = fmaf(0.2989f, __ldg(p), fmaf(0.587f, __ldg(p + 1), 0.114f * __ldg(p + 2)));
            }
            g[r * G_STRIDE + c] = v;
        }
    }
    __syncthreads();

    // ------------- Phase 2+3 fused: specialized per block class -------------
    float* outn = out + (size_t)n * H * W;
    if (!xe && !ye)      lbp_phase23<false, false>(g, outn, x0, by, wrp, lane, H, W);
    else if (!xe)        lbp_phase23<false, true >(g, outn, x0, by, wrp, lane, H, W);
    else if (!ye)        lbp_phase23<true,  false>(g, outn, x0, by, wrp, lane, H, W);
    else                 lbp_phase23<true,  true >(g, outn, x0, by, wrp, lane, H, W);
}

extern "C" void kernel_launch(void* const* d_in, const int* in_sizes, int n_in,
                              void* d_out, int out_size)
{
    const float* in = (const float*)d_in[0];
    float* out = (float*)d_out;

    const int H = 512, W = 512;
    const int N = in_sizes[0] / (H * W * 3);

    dim3 grid(GX, GY, N);   // 9 x 8 x 32 = 2304
    lbp_warp2_kernel<<<grid, NTHREADS>>>(in, out, H, W);
}

// round 13
// speedup vs baseline: 1.1120x; 1.0269x over previous
#include <cuda_runtime.h>
#include <cuda_bf16.h>
#include <cstdint>

// LBP layer, fully fused, warp-strip, two s-columns per lane, edge-specialized,
// packed f32x2 LBP accumulation, single-op FSET compares + balanced add tree.
//   gray = dot(rgb, [0.2989, 0.587, 0.114])                (zero-padded outside)
//   s(y,x) = #{3x3 nbrs (incl. center): gray >= gray(y,x)} (s = 0 outside image)
//   lbp(y,x) = 1*s(y-1,x-1)+2*s(y-1,x)+4*s(y-1,x+1)
//            +128*s(y,x-1)           +8*s(y,x+1)
//            +64*s(y+1,x-1)+32*s(y+1,x)+16*s(y+1,x+1)
// Fixed shapes: N=32, H=W=512, C=3. Output [N,H,W,1] fp32.

#define OUT_PW   60
#define RPW      8
#define NWARPS   4
#define TILE_H   (RPW * NWARPS)        // 32
#define G_COLS   68
#define G_STRIDE 68
#define G_ROWS   (TILE_H + 4)          // 36
#define NTHREADS 128
#define GX 9
#define GY 16

typedef unsigned long long ull;

// ordered >= compare producing 1.0f / 0.0f in ONE instruction (FSET), no select
__device__ __forceinline__ float fge(float a, float b) {
    float r;
    asm("set.ge.f32.f32 %0, %1, %2;" : "=f"(r) : "f"(a), "f"(b));
    return r;
}

// packed-f32x2 helpers
__device__ __forceinline__ ull pk2(float lo, float hi) {
    ull r;
    asm("mov.b64 %0, {%1, %2};" : "=l"(r) : "f"(lo), "f"(hi));
    return r;
}
__device__ __forceinline__ ull ffma2(ull a, ull b, ull c) {
    ull d;
    asm("fma.rn.f32x2 %0, %1, %2, %3;" : "=l"(d) : "l"(a), "l"(b), "l"(c));
    return d;
}
__device__ __forceinline__ ull fmul2(ull a, ull b) {
    ull d;
    asm("mul.rn.f32x2 %0, %1, %2;" : "=l"(d) : "l"(a), "l"(b));
    return d;
}

// weight constants, same fp32 value in both halves
#define WPK(bits) ((((ull)(bits)) << 32) | (ull)(bits))
__device__ const ull W2q   = WPK(0x40000000u);   // (2,2)
__device__ const ull W4q   = WPK(0x40800000u);   // (4,4)
__device__ const ull W8q   = WPK(0x41000000u);   // (8,8)
__device__ const ull W16q  = WPK(0x41800000u);   // (16,16)
__device__ const ull W32q  = WPK(0x42000000u);   // (32,32)
__device__ const ull W64q  = WPK(0x42800000u);   // (64,64)
__device__ const ull W128q = WPK(0x43000000u);   // (128,128)

// Fused neighbor-count + LBP stencil, rolling packed registers, shuffle exchange.
template<bool XE, bool YE>
__device__ __forceinline__ void lbp_phase23(
    const float* __restrict__ g, float* __restrict__ outn,
    int x0, int by, int wrp, int lane, int H, int W)
{
    const int csA = x0 - 1 + 2 * lane;
    const bool colA = XE ? ((unsigned)csA < (unsigned)W) : true;
    const bool colB = XE ? ((unsigned)(csA + 1) < (unsigned)W) : true;
    const int r0 = by * TILE_H + wrp * RPW;

    const float* gp = &g[(wrp * RPW) * G_STRIDE + 2 + 2 * lane];

    float2 va = *(const float2*)(gp);     float2 va2 = *(const float2*)(gp + 2);
    float a0 = va.x, a1 = va.y, a2 = va2.x, a3 = va2.y;   gp += G_STRIDE;
    float2 vb = *(const float2*)(gp);     float2 vb2 = *(const float2*)(gp + 2);
    float b0 = vb.x, b1 = vb.y, b2 = vb2.x, b3 = vb2.y;   gp += G_STRIDE;

    // packed s-pair rolling state: P1=(sa,sb) P2=(sb,na) P3=(na,nb)
    // Q* = two iters ago (weights 1/2/4), R* = one iter ago (128/-/8)
    ull Q1 = 0, Q2 = 0, Q3 = 0;
    ull R1 = 0, R2 = 0, R3 = 0;

    const bool doStore = (lane <= 29);   // lanes 0..29 -> cols x0 .. x0+59
    float* op = outn + (size_t)r0 * W + (x0 + 2 * lane);

    #pragma unroll
    for (int i = 0; i < RPW + 2; i++) {
        const float2 vt  = *(const float2*)(gp);
        const float2 vt2 = *(const float2*)(gp + 2);
        const float t0 = vt.x, t1 = vt.y, t2 = vt2.x, t3 = vt2.y;
        gp += G_STRIDE;

        // 16 independent single-op FSET compares + balanced add trees
        const float eA0 = fge(a0, b1), eA1 = fge(a1, b1), eA2 = fge(a2, b1);
        const float eA3 = fge(b0, b1), eA4 = fge(b2, b1);
        const float eA5 = fge(t0, b1), eA6 = fge(t1, b1), eA7 = fge(t2, b1);
        const float eB0 = fge(a1, b2), eB1 = fge(a2, b2), eB2 = fge(a3, b2);
        const float eB3 = fge(b1, b2), eB4 = fge(b3, b2);
        const float eB5 = fge(t1, b2), eB6 = fge(t2, b2), eB7 = fge(t3, b2);

        const float cA = ((eA0 + eA1) + (eA2 + eA3))
                       + (((eA4 + eA5) + (eA6 + eA7)) + 1.0f);
        const float cB = ((eB0 + eB1) + (eB2 + eB3))
                       + (((eB4 + eB5) + (eB6 + eB7)) + 1.0f);

        float sa, sb;
        if (YE) {
            const int ys = r0 - 1 + i;
            const bool rowOk = (unsigned)ys < (unsigned)H;
            sa = (rowOk && colA) ? cA : 0.0f;     // zero-pad s
            sb = (rowOk && colB) ? cB : 0.0f;
        } else if (XE) {
            sa = colA ? cA : 0.0f;
            sb = colB ? cB : 0.0f;
        } else {
            sa = cA;
            sb = cB;
        }

        const float na = __shfl_down_sync(0xffffffffu, sa, 1);  // s col csA+2
        const float nb = __shfl_down_sync(0xffffffffu, sb, 1);  // s col csA+3

        const ull P1 = pk2(sa, sb);
        const ull P2 = pk2(sb, na);
        const ull P3 = pk2(na, nb);

        if (i >= 2) {
            // (v0,v1) = 1*Q1 + 2*Q2 + 4*Q3 + 128*R1 + 8*R3 + 64*P1 + 32*P2 + 16*P3
            ull vA = Q1;
            vA = ffma2(Q2, W2q,   vA);
            vA = ffma2(Q3, W4q,   vA);
            vA = ffma2(R1, W128q, vA);
            ull vB = fmul2(R3, W8q);
            vB = ffma2(P1, W64q, vB);
            vB = ffma2(P2, W32q, vB);
            vB = ffma2(P3, W16q, vB);
            ull v;
            asm("add.rn.f32x2 %0, %1, %2;" : "=l"(v) : "l"(vA), "l"(vB));
            if (doStore) *(ull*)op = v;            // two fp32 outputs, 8B aligned
            op += W;
        }

        Q1 = R1; Q2 = R2; Q3 = R3;
        R1 = P1; R2 = P2; R3 = P3;
        a0 = b0; a1 = b1; a2 = b2; a3 = b3;
        b0 = t0; b1 = t1; b2 = t2; b3 = t3;
    }
}

__global__ __launch_bounds__(NTHREADS, 10) void lbp_warp2_kernel(
    const float* __restrict__ in,   // [N, H, W, 3]
    float* __restrict__ out,        // [N, H, W, 1]
    int H, int W)
{
    __shared__ __align__(16) float g[G_ROWS * G_STRIDE];   // 9.56 KB

    const int tid  = threadIdx.x;
    const int lane = tid & 31;
    const int wrp  = tid >> 5;
    const int bx = blockIdx.x, by = blockIdx.y, n = blockIdx.z;

    const bool xe = (bx == 0) || (bx == GX - 1);
    const bool ye = (by == 0) || (by == GY - 1);

    int x0 = bx * OUT_PW;
    if (x0 + OUT_PW > W) x0 = W - OUT_PW;     // 452 for last block (%4==0)
    const int gx0a = x0 - 4;
    const int gy0 = by * TILE_H - 2;

    const float* __restrict__ base = in + (size_t)n * H * W * 3;

    // ---------------- Phase 1: RGB -> gray into smem ----------------
    if (!xe) {
        if (!ye) {
            #pragma unroll 4
            for (int idx = tid; idx < G_ROWS * (G_COLS / 4); idx += NTHREADS) {
                const int r  = idx / (G_COLS / 4);
                const int pc = idx - r * (G_COLS / 4);
                const int gy = gy0 + r;
                const int gx = gx0a + 4 * pc;
                const float4* p = (const float4*)(base + ((size_t)gy * W + gx) * 3);
                const float4 q0 = __ldg(p + 0);
                const float4 q1 = __ldg(p + 1);
                const float4 q2 = __ldg(p + 2);
                float4 go;
                go.x = fmaf(0.2989f, q0.x, fmaf(0.587f, q0.y, 0.114f * q0.z));
                go.y = fmaf(0.2989f, q0.w, fmaf(0.587f, q1.x, 0.114f * q1.y));
                go.z = fmaf(0.2989f, q1.z, fmaf(0.587f, q1.w, 0.114f * q2.x));
                go.w = fmaf(0.2989f, q2.y, fmaf(0.587f, q2.z, 0.114f * q2.w));
                *(float4*)&g[r * G_STRIDE + 4 * pc] = go;
            }
        } else {
            #pragma unroll 4
            for (int idx = tid; idx < G_ROWS * (G_COLS / 4); idx += NTHREADS) {
                const int r  = idx / (G_COLS / 4);
                const int pc = idx - r * (G_COLS / 4);
                const int gy = gy0 + r;
                float4 go = make_float4(0.f, 0.f, 0.f, 0.f);
                if ((unsigned)gy < (unsigned)H) {
                    const int gx = gx0a + 4 * pc;
                    const float4* p = (const float4*)(base + ((size_t)gy * W + gx) * 3);
                    const float4 q0 = __ldg(p + 0);
                    const float4 q1 = __ldg(p + 1);
                    const float4 q2 = __ldg(p + 2);
                    go.x = fmaf(0.2989f, q0.x, fmaf(0.587f, q0.y, 0.114f * q0.z));
                    go.y = fmaf(0.2989f, q0.w, fmaf(0.587f, q1.x, 0.114f * q1.y));
                    go.z = fmaf(0.2989f, q1.z, fmaf(0.587f, q1.w, 0.114f * q2.x));
                    go.w = fmaf(0.2989f, q2.y, fmaf(0.587f, q2.z, 0.114f * q2.w));
                }
                *(float4*)&g[r * G_STRIDE + 4 * pc] = go;
            }
        }
    } else {
        #pragma unroll 4
        for (int idx = tid; idx < G_ROWS * G_COLS; idx += NTHREADS) {
            const int r = idx / G_COLS;
            const int c = idx - r * G_COLS;
            const int gy = gy0 + r;
            const int gx = gx0a + c;
            float v = 0.0f;
            if ((unsigned)gy < (unsigned)H && (unsigned)gx < (unsigned)W) {
                const float* p = base + ((size_t)gy * W + gx) * 3;
                v = fmaf(0.2989f, __ldg(p), fmaf(0.587f, __ldg(p + 1), 0.114f * __ldg(p + 2)));
            }
            g[r * G_STRIDE + c] = v;
        }
    }
    __syncthreads();

    // ------------- Phase 2+3 fused: specialized per block class -------------
    float* outn = out + (size_t)n * H * W;
    if (!xe && !ye)      lbp_phase23<false, false>(g, outn, x0, by, wrp, lane, H, W);
    else if (!xe)        lbp_phase23<false, true >(g, outn, x0, by, wrp, lane, H, W);
    else if (!ye)        lbp_phase23<true,  false>(g, outn, x0, by, wrp, lane, H, W);
    else                 lbp_phase23<true,  true >(g, outn, x0, by, wrp, lane, H, W);
}

extern "C" void kernel_launch(void* const* d_in, const int* in_sizes, int n_in,
                              void* d_out, int out_size)
{
    const float* in = (const float*)d_in[0];
    float* out = (float*)d_out;

    const int H = 512, W = 512;
    const int N = in_sizes[0] / (H * W * 3);

    dim3 grid(GX, GY, N);   // 9 x 16 x 32 = 4608
    lbp_warp2_kernel<<<grid, NTHREADS>>>(in, out, H, W);
}

// round 14
// speedup vs baseline: 1.3358x; 1.2013x over previous
#include <cuda_runtime.h>
#include <cuda_bf16.h>
#include <cstdint>

// LBP layer, fully fused, ZERO-SMEM warp-strip design:
// each lane loads its own 2 RGB pixels per row straight from GMEM (coalesced
// float2 x3), computes gray, gets +2/+3 columns via shfl_down, then the
// validated rolling compare + packed-f32x2 LBP core (identical to R10).
// No shared memory, no __syncthreads, software-pipelined loads.
//   gray = dot(rgb, [0.2989, 0.587, 0.114])                (zero-padded outside)
//   s(y,x) = #{3x3 nbrs (incl. center): gray >= gray(y,x)} (s = 0 outside image)
//   lbp(y,x) = 1*s(y-1,x-1)+2*s(y-1,x)+4*s(y-1,x+1)
//            +128*s(y,x-1)           +8*s(y,x+1)
//            +64*s(y+1,x-1)+32*s(y+1,x)+16*s(y+1,x+1)
// Fixed shapes: N=32, H=W=512, C=3. Output [N,H,W,1] fp32.

#define OUT_PW   60          // output cols per x-tile (x0 % 4 == 0)
#define RPW      16          // output rows per warp strip
#define WARPS_PB 2           // warps per block (stacked vertically)
#define NTHREADS 64
#define GX 9
#define GYB 16               // blocks in y: each covers WARPS_PB*RPW = 32 rows

typedef unsigned long long ull;

// packed-f32x2 helpers
__device__ __forceinline__ ull pk2(float lo, float hi) {
    ull r;
    asm("mov.b64 %0, {%1, %2};" : "=l"(r) : "f"(lo), "f"(hi));
    return r;
}
__device__ __forceinline__ ull ffma2(ull a, ull b, ull c) {
    ull d;
    asm("fma.rn.f32x2 %0, %1, %2, %3;" : "=l"(d) : "l"(a), "l"(b), "l"(c));
    return d;
}
__device__ __forceinline__ ull fmul2(ull a, ull b) {
    ull d;
    asm("mul.rn.f32x2 %0, %1, %2;" : "=l"(d) : "l"(a), "l"(b));
    return d;
}

#define WPK(bits) ((((ull)(bits)) << 32) | (ull)(bits))
__device__ const ull W2q   = WPK(0x40000000u);
__device__ const ull W4q   = WPK(0x40800000u);
__device__ const ull W8q   = WPK(0x41000000u);
__device__ const ull W16q  = WPK(0x41800000u);
__device__ const ull W32q  = WPK(0x42000000u);
__device__ const ull W64q  = WPK(0x42800000u);
__device__ const ull W128q = WPK(0x43000000u);

struct Raw { float2 p0, p1, p2; };

__device__ __forceinline__ Raw ldraw(const float* __restrict__ p, bool ok) {
    Raw r;
    if (ok) {
        r.p0 = __ldg((const float2*)p);
        r.p1 = __ldg((const float2*)(p + 2));
        r.p2 = __ldg((const float2*)(p + 4));
    } else {
        r.p0 = make_float2(0.f, 0.f);
        r.p1 = make_float2(0.f, 0.f);
        r.p2 = make_float2(0.f, 0.f);
    }
    return r;
}

__device__ __forceinline__ void gray2(const Raw& r, float& g0, float& g1) {
    g0 = fmaf(0.2989f, r.p0.x, fmaf(0.587f, r.p0.y, 0.114f * r.p1.x));
    g1 = fmaf(0.2989f, r.p1.y, fmaf(0.587f, r.p2.x, 0.114f * r.p2.y));
}

// One warp strip: RPW output rows x 62 s-cols (60 stored), rolling registers.
template<bool XE, bool YE>
__device__ __forceinline__ void lbp_strip(
    const float* __restrict__ base,   // image n, RGB
    float* __restrict__ outn,         // image n, out
    int x0, int r0, int lane, int H, int W)
{
    const int c0  = x0 - 2 + 2 * lane;        // lane's gray cols c0, c0+1 (even)
    const int csA = c0 + 1;                   // lane's s cols csA, csA+1
    const bool colA = XE ? ((unsigned)csA       < (unsigned)W) : true;
    const bool colB = XE ? ((unsigned)(csA + 1) < (unsigned)W) : true;
    const bool ldOk = XE ? ((c0 >= 0) && (c0 < W)) : true;   // both-or-neither (even)

    const long long rstep = (long long)W * 3;
    const float* rpA = base + ((long long)(r0 - 2) * W + c0) * 3;

    // preamble: rows r0-2, r0-1; prefetch row r0
    const bool okA = ldOk && (!YE || (unsigned)(r0 - 2) < (unsigned)H);
    Raw ra = ldraw(rpA, okA);
    const bool okB = ldOk && (!YE || (unsigned)(r0 - 1) < (unsigned)H);
    Raw rb = ldraw(rpA + rstep, okB);
    Raw rq = ldraw(rpA + 2 * rstep, ldOk);    // row r0: always in [0,H)
    const float* rpn = rpA + 3 * rstep;       // next prefetch: row r0+1

    float a0, a1; gray2(ra, a0, a1);
    float a2 = __shfl_down_sync(0xffffffffu, a0, 1);   // col c0+2
    float a3 = __shfl_down_sync(0xffffffffu, a1, 1);   // col c0+3
    float b0, b1; gray2(rb, b0, b1);
    float b2 = __shfl_down_sync(0xffffffffu, b0, 1);
    float b3 = __shfl_down_sync(0xffffffffu, b1, 1);

    // packed s-pair rolling state (identical to R10)
    ull Q1 = 0, Q2 = 0, Q3 = 0;
    ull R1 = 0, R2 = 0, R3 = 0;

    const bool doStore = (lane <= 29);        // lanes 0..29 -> cols x0 .. x0+59
    float* op = outn + (size_t)r0 * W + (x0 + 2 * lane);

    #pragma unroll
    for (int i = 0; i < RPW + 2; i++) {
        const Raw cur = rq;
        if (i < RPW + 1) {                    // prefetch row r0+i+1
            const bool okn = ldOk && (!YE || (r0 + i + 1) < H);
            rq = ldraw(rpn, okn);
            rpn += rstep;
        }
        float t0, t1; gray2(cur, t0, t1);
        const float t2 = __shfl_down_sync(0xffffffffu, t0, 1);
        const float t3 = __shfl_down_sync(0xffffffffu, t1, 1);

        // two independent compare-accumulate chains (centers b1, b2) — as R10
        float cA = 1.0f, cB = 1.0f;
        cA += (a0 >= b1) ? 1.0f : 0.0f;
        cB += (a1 >= b2) ? 1.0f : 0.0f;
        cA += (a1 >= b1) ? 1.0f : 0.0f;
        cB += (a2 >= b2) ? 1.0f : 0.0f;
        cA += (a2 >= b1) ? 1.0f : 0.0f;
        cB += (a3 >= b2) ? 1.0f : 0.0f;
        cA += (b0 >= b1) ? 1.0f : 0.0f;
        cB += (b1 >= b2) ? 1.0f : 0.0f;
        cA += (b2 >= b1) ? 1.0f : 0.0f;
        cB += (b3 >= b2) ? 1.0f : 0.0f;
        cA += (t0 >= b1) ? 1.0f : 0.0f;
        cB += (t1 >= b2) ? 1.0f : 0.0f;
        cA += (t1 >= b1) ? 1.0f : 0.0f;
        cB += (t2 >= b2) ? 1.0f : 0.0f;
        cA += (t2 >= b1) ? 1.0f : 0.0f;
        cB += (t3 >= b2) ? 1.0f : 0.0f;

        float sa, sb;
        if (YE) {
            const int ys = r0 - 1 + i;
            const bool rowOk = (unsigned)ys < (unsigned)H;
            sa = (rowOk && colA) ? cA : 0.0f;     // zero-pad s
            sb = (rowOk && colB) ? cB : 0.0f;
        } else if (XE) {
            sa = colA ? cA : 0.0f;
            sb = colB ? cB : 0.0f;
        } else {
            sa = cA;
            sb = cB;
        }

        const float na = __shfl_down_sync(0xffffffffu, sa, 1);  // s col csA+2
        const float nb = __shfl_down_sync(0xffffffffu, sb, 1);  // s col csA+3

        const ull P1 = pk2(sa, sb);
        const ull P2 = pk2(sb, na);
        const ull P3 = pk2(na, nb);

        if (i >= 2) {
            // (v0,v1) = 1*Q1 + 2*Q2 + 4*Q3 + 128*R1 + 8*R3 + 64*P1 + 32*P2 + 16*P3
            ull vA = Q1;
            vA = ffma2(Q2, W2q,   vA);
            vA = ffma2(Q3, W4q,   vA);
            vA = ffma2(R1, W128q, vA);
            ull vB = fmul2(R3, W8q);
            vB = ffma2(P1, W64q, vB);
            vB = ffma2(P2, W32q, vB);
            vB = ffma2(P3, W16q, vB);
            ull v;
            asm("add.rn.f32x2 %0, %1, %2;" : "=l"(v) : "l"(vA), "l"(vB));
            if (doStore) *(ull*)op = v;            // two fp32 outputs, 8B aligned
            op += W;
        }

        Q1 = R1; Q2 = R2; Q3 = R3;
        R1 = P1; R2 = P2; R3 = P3;
        a0 = b0; a1 = b1; a2 = b2; a3 = b3;
        b0 = t0; b1 = t1; b2 = t2; b3 = t3;
    }
}

__global__ __launch_bounds__(NTHREADS, 12) void lbp_nosmem_kernel(
    const float* __restrict__ in,   // [N, H, W, 3]
    float* __restrict__ out,        // [N, H, W, 1]
    int H, int W)
{
    const int lane = threadIdx.x & 31;
    const int wrp  = threadIdx.x >> 5;
    const int bx = blockIdx.x, byb = blockIdx.y, n = blockIdx.z;

    const bool xe = (bx == 0) || (bx == GX - 1);
    const bool ye = (byb == 0) || (byb == GYB - 1);

    int x0 = bx * OUT_PW;
    if (x0 + OUT_PW > W) x0 = W - OUT_PW;     // 452 for last block (%4==0)
    const int r0 = (byb * WARPS_PB + wrp) * RPW;

    const float* base = in + (size_t)n * H * W * 3;
    float* outn = out + (size_t)n * H * W;

    if (!xe && !ye)      lbp_strip<false, false>(base, outn, x0, r0, lane, H, W);
    else if (!xe)        lbp_strip<false, true >(base, outn, x0, r0, lane, H, W);
    else if (!ye)        lbp_strip<true,  false>(base, outn, x0, r0, lane, H, W);
    else                 lbp_strip<true,  true >(base, outn, x0, r0, lane, H, W);
}

extern "C" void kernel_launch(void* const* d_in, const int* in_sizes, int n_in,
                              void* d_out, int out_size)
{
    const float* in = (const float*)d_in[0];
    float* out = (float*)d_out;

    const int H = 512, W = 512;
    const int N = in_sizes[0] / (H * W * 3);

    dim3 grid(GX, GYB, N);   // 9 x 16 x 32 = 4608 blocks of 64 threads
    lbp_nosmem_kernel<<<grid, NTHREADS>>>(in, out, H, W);
}